// round 13
// baseline (speedup 1.0000x reference)
#include <cuda_runtime.h>
#include <cuda_bf16.h>
#include <cstdint>

// BilinearInterpolation (spatial transformer grid sample)
// X: [B, C, H, W] fp32, theta: [B, 6] fp32 -> out: [B, C, H_OUT, W_OUT] fp32
//
// R12 = R11 with the skew-overlap bug fixed: row slot stride is now
// bwp = bw4 + 32 (>= max skew 28 + row length), so the per-row 16B skew
// ((r&7)*4 floats) can never alias the next row. Skew keeps 8 bank phases
// across rows (kills the R10 4-way LDS conflicts) at intact cp.async
// 16B alignment. Staged values bit-exact; weight chain identical to
// R2-R4: rel_err must return to exactly 9.128e-4.

namespace {
constexpr int B = 16, C = 64, H = 256, W = 256;
constexpr int H_OUT = 256, W_OUT = 256;
constexpr int HW  = H * W;
constexpr int HWO = H_OUT * W_OUT;
constexpr int TILE = 32;            // 32x32 output tile
constexpr int CG   = 16;            // channels per block
constexpr int NCG  = C / CG;        // 4
constexpr int NTX  = W_OUT / TILE;  // 8
constexpr int BUF  = 5632;          // floats per buffer; 2 bufs = 45KB
}

__device__ __forceinline__ void cp_async16(uint32_t smem_addr, const void* gptr) {
    asm volatile("cp.async.cg.shared.global [%0], [%1], 16;\n"
                 :: "r"(smem_addr), "l"(gptr));
}
__device__ __forceinline__ void cp_async_commit() {
    asm volatile("cp.async.commit_group;\n" ::: "memory");
}
__device__ __forceinline__ void cp_async_wait_all() {
    asm volatile("cp.async.wait_group 0;\n" ::: "memory");
}

__global__ __launch_bounds__(256, 5)
void bilerp_kernel(const float* __restrict__ X,
                   const float* __restrict__ theta,
                   float* __restrict__ out) {
    __shared__ __align__(16) float buf0[BUF];
    __shared__ __align__(16) float buf1[BUF];

    // blockIdx = b*256 + tile*4 + cg
    const int cg = blockIdx.x & (NCG - 1);
    const int t  = (blockIdx.x >> 2) & 63;
    const int b  = blockIdx.x >> 8;
    const int tx = (t & (NTX - 1)) * TILE;
    const int ty = (t >> 3) * TILE;

    const int lane = threadIdx.x & 31;
    const int w    = threadIdx.x >> 5;   // 0..7

    const float* th = theta + b * 6;
    const float t00 = __ldg(th + 0), t01 = __ldg(th + 1), t02 = __ldg(th + 2);
    const float t10 = __ldg(th + 3), t11 = __ldg(th + 4), t12 = __ldg(th + 5);

    // ---- tile bbox from the 4 tile corners (affine map is linear) + pad ----
    const float cxl = fmaf((float)tx,        2.0f / 255.0f, -1.0f);
    const float cxh = fmaf((float)(tx + 31), 2.0f / 255.0f, -1.0f);
    const float cyl = fmaf((float)ty,        2.0f / 255.0f, -1.0f);
    const float cyh = fmaf((float)(ty + 31), 2.0f / 255.0f, -1.0f);

    float xmn = 3.0e38f, xmx = -3.0e38f, ymn = 3.0e38f, ymx = -3.0e38f;
    #pragma unroll
    for (int k = 0; k < 4; ++k) {
        const float xck = (k & 1) ? cxh : cxl;
        const float yck = (k & 2) ? cyh : cyl;
        const float xs = t00 * xck + t01 * yck + t02;
        const float ys = t10 * xck + t11 * yck + t12;
        const float xx = (xs + 1.0f) * 128.0f;
        const float yy = (ys + 1.0f) * 128.0f;
        xmn = fminf(xmn, xx); xmx = fmaxf(xmx, xx);
        ymn = fminf(ymn, yy); ymx = fmaxf(ymx, yy);
    }
    const int xlo = min(max((int)floorf(xmn) - 1, 0), W - 1);
    const int xhi = min(max((int)floorf(xmx) + 2, 0), W - 1);
    const int ylo = min(max((int)floorf(ymn) - 1, 0), H - 1);
    const int yhi = min(max((int)floorf(ymx) + 2, 0), H - 1);

    // 16B-aligned staging window (X rows are 1KB-aligned)
    const int xlo4 = xlo & ~3;
    const int bw4  = ((xhi - xlo4) | 3) + 1;   // multiple of 4, covers xhi
    const int bh   = yhi - ylo + 1;
    const int bwp  = bw4 + 32;                 // slot stride: covers skew<=28
    const int nch  = bw4 >> 2;                 // 16B chunks per row (>=1)

    const float* __restrict__ xbase = X   + ((size_t)(b * C + cg * CG)) * HW;
    float*       __restrict__ obase = out + ((size_t)(b * C + cg * CG)) * HWO;

    const bool fits = (bwp * bh <= BUF);       // block-uniform

    if (fits) {
        // ===== staged path =====
        // thread -> pixels (tx+lane, ty + w + 8*i), i = 0..3
        int   la[4], lb[4], lc[4], ld[4];
        float wA[4], wB[4], wC[4], wD[4];
        #pragma unroll
        for (int i = 0; i < 4; ++i) {
            const int ix = tx + lane;
            const int iy = ty + w + 8 * i;

            const float xc = fmaf((float)ix, 2.0f / (float)(W_OUT - 1), -1.0f);
            const float yc = fmaf((float)iy, 2.0f / (float)(H_OUT - 1), -1.0f);
            const float xs = t00 * xc + t01 * yc + t02;
            const float ys = t10 * xc + t11 * yc + t12;
            const float x  = (xs + 1.0f) * ((float)W * 0.5f);
            const float y  = (ys + 1.0f) * ((float)H * 0.5f);

            int x0 = (int)floorf(x);
            int x1 = x0 + 1;
            int y0 = (int)floorf(y);
            int y1 = y0 + 1;
            x0 = min(max(x0, 0), W - 1);
            x1 = min(max(x1, 0), W - 1);
            y0 = min(max(y0, 0), H - 1);
            y1 = min(max(y1, 0), H - 1);

            const float x0f = (float)x0, x1f = (float)x1;
            const float y0f = (float)y0, y1f = (float)y1;
            wA[i] = (x1f - x) * (y1f - y);
            wB[i] = (x1f - x) * (y - y0f);
            wC[i] = (x - x0f) * (y1f - y);
            wD[i] = (x - x0f) * (y - y0f);

            const int r0 = y0 - ylo, r1 = y1 - ylo;
            const int s0 = r0 * bwp + ((r0 & 7) << 2);   // skewed row base
            const int s1 = r1 * bwp + ((r1 & 7) << 2);
            la[i] = s0 + (x0 - xlo4);
            lb[i] = s1 + (x0 - xlo4);
            lc[i] = s0 + (x1 - xlo4);
            ld[i] = s1 + (x1 - xlo4);
        }

        // flat staging: pow2-rounded chunk grid, predicated cp.async
        const int ls    = (nch > 1) ? (32 - __clz(nch - 1)) : 0;  // ceil log2
        const int nch2m = (1 << ls) - 1;
        const int tot   = bh << ls;
        const uint32_t sb0 = (uint32_t)__cvta_generic_to_shared(buf0);
        const uint32_t sb1 = (uint32_t)__cvta_generic_to_shared(buf1);
        const int tid = threadIdx.x;

        auto stage = [&](int c, uint32_t db) {
            const float* src = xbase + (size_t)c * HW + (size_t)ylo * W + xlo4;
            for (int idx = tid; idx < tot; idx += 256) {
                const int r = idx >> ls;
                const int q = idx & nch2m;
                if (q < nch) {
                    const uint32_t row = (uint32_t)(r * bwp + ((r & 7) << 2)) * 4u;
                    cp_async16(db + row + (uint32_t)q * 16u,
                               src + (size_t)r * W + q * 4);
                }
            }
            cp_async_commit();
        };

        const size_t orow = (size_t)(ty + w) * W_OUT + tx + lane;

        stage(0, sb0);
        #pragma unroll
        for (int cc = 0; cc < CG; cc += 2) {
            // ---- even channel: gather from buf0 ----
            cp_async_wait_all();
            __syncthreads();
            if (cc + 1 < CG) stage(cc + 1, sb1);
            {
                float* op = obase + (size_t)cc * HWO + orow;
                #pragma unroll
                for (int i = 0; i < 4; ++i) {
                    const float pa = buf0[la[i]];
                    const float pb = buf0[lb[i]];
                    const float pc = buf0[lc[i]];
                    const float pd = buf0[ld[i]];
                    op[(size_t)(8 * i) * W_OUT] =
                        wA[i] * pa + wB[i] * pb + wC[i] * pc + wD[i] * pd;
                }
            }
            // ---- odd channel: gather from buf1 ----
            cp_async_wait_all();
            __syncthreads();
            if (cc + 2 < CG) stage(cc + 2, sb0);
            {
                float* op = obase + (size_t)(cc + 1) * HWO + orow;
                #pragma unroll
                for (int i = 0; i < 4; ++i) {
                    const float pa = buf1[la[i]];
                    const float pb = buf1[lb[i]];
                    const float pc = buf1[lc[i]];
                    const float pd = buf1[ld[i]];
                    op[(size_t)(8 * i) * W_OUT] =
                        wA[i] * pa + wB[i] * pb + wC[i] * pc + wD[i] * pd;
                }
            }
        }
    } else {
        // ===== fallback: direct gathers, R4-winning 8x4 warp patch =====
        const int lx = lane & 7;
        const int ly = lane >> 3;
        const int wx = w & 3;
        const int wy = w >> 2;

        int   ga[4], gb[4], gc[4], gd[4];
        float wA[4], wB[4], wC[4], wD[4];
        #pragma unroll
        for (int i = 0; i < 4; ++i) {
            const int ix = tx + wx * 8 + lx;
            const int iy = ty + wy * 4 + ly + 8 * i;

            const float xc = fmaf((float)ix, 2.0f / (float)(W_OUT - 1), -1.0f);
            const float yc = fmaf((float)iy, 2.0f / (float)(H_OUT - 1), -1.0f);
            const float xs = t00 * xc + t01 * yc + t02;
            const float ys = t10 * xc + t11 * yc + t12;
            const float x  = (xs + 1.0f) * ((float)W * 0.5f);
            const float y  = (ys + 1.0f) * ((float)H * 0.5f);

            int x0 = (int)floorf(x);
            int x1 = x0 + 1;
            int y0 = (int)floorf(y);
            int y1 = y0 + 1;
            x0 = min(max(x0, 0), W - 1);
            x1 = min(max(x1, 0), W - 1);
            y0 = min(max(y0, 0), H - 1);
            y1 = min(max(y1, 0), H - 1);

            const float x0f = (float)x0, x1f = (float)x1;
            const float y0f = (float)y0, y1f = (float)y1;
            wA[i] = (x1f - x) * (y1f - y);
            wB[i] = (x1f - x) * (y - y0f);
            wC[i] = (x - x0f) * (y1f - y);
            wD[i] = (x - x0f) * (y - y0f);
            ga[i] = y0 * W + x0;
            gb[i] = y1 * W + x0;
            gc[i] = y0 * W + x1;
            gd[i] = y1 * W + x1;
        }

        const int ox = tx + wx * 8 + lx;
        const int oy = ty + wy * 4 + ly;
        for (int c = 0; c < CG; ++c) {
            const float* p = xbase + (size_t)c * HW;
            float* op = obase + (size_t)c * HWO + (size_t)oy * W_OUT + ox;
            #pragma unroll
            for (int i = 0; i < 4; ++i) {
                const float pa = __ldg(p + ga[i]);
                const float pb = __ldg(p + gb[i]);
                const float pc = __ldg(p + gc[i]);
                const float pd = __ldg(p + gd[i]);
                op[(size_t)(8 * i) * W_OUT] =
                    wA[i] * pa + wB[i] * pb + wC[i] * pc + wD[i] * pd;
            }
        }
    }
}

extern "C" void kernel_launch(void* const* d_in, const int* in_sizes, int n_in,
                              void* d_out, int out_size) {
    const float* X     = (const float*)d_in[0];
    const float* theta = (const float*)d_in[1];
    if (n_in >= 2 && in_sizes[0] == B * 6) {
        theta = (const float*)d_in[0];
        X     = (const float*)d_in[1];
    }
    float* out = (float*)d_out;

    dim3 grid(B * 64 * NCG);   // 4096 blocks
    dim3 block(256);
    bilerp_kernel<<<grid, block>>>(X, theta, out);
}

// round 14
// speedup vs baseline: 1.3383x; 1.3383x over previous
#include <cuda_runtime.h>
#include <cuda_bf16.h>

// BilinearInterpolation (spatial transformer grid sample)
// X: [B, C, H, W] fp32, theta: [B, 6] fp32 -> out: [B, C, H_OUT, W_OUT] fp32
//
// R13 = R4 (scalar direct gathers + warp-uniform clamp specialization),
// plus ONE isolated change: per-batch adaptive warp shape.
// Warp patch (wx,wy) in {(16,2),(8,4),(4,8),(2,16)} inside a 16x16 block
// tile, chosen by a block-uniform cost model on theta (gather lines per
// LDG ~ wx|t10|+wy|t11|+1 rows x col factor, + wy store rows). Isotropic
// batches degenerate to R4's 8x4. Pure thread->pixel remap: arithmetic
// identical to R2-R4, rel_err must stay exactly 9.128e-4.

namespace {
constexpr int B = 16, C = 64, H = 256, W = 256;
constexpr int H_OUT = 256, W_OUT = 256;
constexpr int HW  = H * W;           // channel stride in X
constexpr int HWO = H_OUT * W_OUT;   // channel stride in out
constexpr int NBX = W_OUT / 16;      // 16
constexpr int NBY = H_OUT / 16;      // 16
}

__global__ __launch_bounds__(256, 6)
void bilerp_kernel(const float* __restrict__ X,
                   const float* __restrict__ theta,
                   float* __restrict__ out) {
    // Block decode: blockIdx.x = b*256 + by*16 + bx  (16x16 pixel tile)
    const int bx = blockIdx.x & (NBX - 1);
    const int by = (blockIdx.x >> 4) & (NBY - 1);
    const int b  = blockIdx.x >> 8;

    const int lane = threadIdx.x & 31;
    const int w    = threadIdx.x >> 5;      // 0..7

    const float* th = theta + b * 6;
    const float t00 = __ldg(th + 0), t01 = __ldg(th + 1), t02 = __ldg(th + 2);
    const float t10 = __ldg(th + 3), t11 = __ldg(th + 4), t12 = __ldg(th + 5);

    // ---- adaptive warp shape: wx = 1<<sx, wy = 32>>sx, sx in {4,3,2,1} ----
    // cost ~ (avg gather LDGs) * rows * colfactor + store rows
    const float ax0 = fabsf(t00), ax1 = fabsf(t01);
    const float ay0 = fabsf(t10), ay1 = fabsf(t11);
    int   sx_best = 3;
    float c_best  = 3.0e38f;
    #pragma unroll
    for (int s = 4; s >= 1; --s) {
        const float wxf = (float)(1 << s);
        const float wyf = (float)(32 >> s);
        const float rows = wxf * ay0 + wyf * ay1 + 1.0f;
        const float cols = wxf * ax0 + wyf * ax1 + 2.0f;
        const float cost = 2.3f * rows * (1.0f + cols * 0.03125f) + wyf;
        if (cost < c_best) { c_best = cost; sx_best = s; }
    }
    const int sx  = sx_best;                // uniform across block (per batch)
    const int lx  = lane & ((1 << sx) - 1);
    const int ly  = lane >> sx;
    const int wox = (w & ((1 << (4 - sx)) - 1)) << sx;
    const int woy = (w >> (4 - sx)) << (5 - sx);

    const int ix = bx * 16 + wox + lx;
    const int iy = by * 16 + woy + ly;

    // ---- identical arithmetic chain (R2..R4) ----
    const float xc = fmaf((float)ix, 2.0f / (float)(W_OUT - 1), -1.0f);
    const float yc = fmaf((float)iy, 2.0f / (float)(H_OUT - 1), -1.0f);

    const float xs = t00 * xc + t01 * yc + t02;
    const float ys = t10 * xc + t11 * yc + t12;

    const float x = (xs + 1.0f) * ((float)W * 0.5f);
    const float y = (ys + 1.0f) * ((float)H * 0.5f);

    int x0 = (int)floorf(x);
    int x1 = x0 + 1;
    int y0 = (int)floorf(y);
    int y1 = y0 + 1;
    x0 = min(max(x0, 0), W - 1);
    x1 = min(max(x1, 0), W - 1);
    y0 = min(max(y0, 0), H - 1);
    y1 = min(max(y1, 0), H - 1);

    const float x0f = (float)x0, x1f = (float)x1;
    const float y0f = (float)y0, y1f = (float)y1;

    const float wa = (x1f - x) * (y1f - y);
    const float wb = (x1f - x) * (y - y0f);
    const float wc = (x - x0f) * (y1f - y);
    const float wd = (x - x0f) * (y - y0f);

    const int oa = y0 * W + x0;   // == oc when x0==x1 ; == ob when y0==y1
    const int ob = y1 * W + x0;
    const int oc = y0 * W + x1;
    const int od = y1 * W + x1;

    const float* __restrict__ xp = X + (size_t)b * C * HW;
    float* __restrict__ op = out + (size_t)b * C * HWO + (size_t)iy * W_OUT + ix;

    const unsigned full = 0xFFFFFFFFu;
    const bool allx = __all_sync(full, x0 == x1);
    const bool ally = __all_sync(full, y0 == y1);

    if (allx & ally) {
        // oa==ob==oc==od: one load feeds all four corners (bit-identical)
        #pragma unroll 8
        for (int c = 0; c < C; ++c) {
            const float* p = xp + (size_t)c * HW;
            const float pa = __ldg(p + oa);
            op[(size_t)c * HWO] = wa * pa + wb * pa + wc * pa + wd * pa;
        }
    } else if (allx) {
        // oc==oa, od==ob
        #pragma unroll 8
        for (int c = 0; c < C; ++c) {
            const float* p = xp + (size_t)c * HW;
            const float pa = __ldg(p + oa);
            const float pb = __ldg(p + ob);
            op[(size_t)c * HWO] = wa * pa + wb * pb + wc * pa + wd * pb;
        }
    } else if (ally) {
        // ob==oa, od==oc
        #pragma unroll 8
        for (int c = 0; c < C; ++c) {
            const float* p = xp + (size_t)c * HW;
            const float pa = __ldg(p + oa);
            const float pc = __ldg(p + oc);
            op[(size_t)c * HWO] = wa * pa + wb * pa + wc * pc + wd * pc;
        }
    } else {
        #pragma unroll 8
        for (int c = 0; c < C; ++c) {
            const float* p = xp + (size_t)c * HW;
            const float pa = __ldg(p + oa);
            const float pb = __ldg(p + ob);
            const float pc = __ldg(p + oc);
            const float pd = __ldg(p + od);
            op[(size_t)c * HWO] = wa * pa + wb * pb + wc * pc + wd * pd;
        }
    }
}

extern "C" void kernel_launch(void* const* d_in, const int* in_sizes, int n_in,
                              void* d_out, int out_size) {
    const float* X     = (const float*)d_in[0];
    const float* theta = (const float*)d_in[1];
    if (n_in >= 2 && in_sizes[0] == B * 6) {
        theta = (const float*)d_in[0];
        X     = (const float*)d_in[1];
    }
    float* out = (float*)d_out;

    dim3 grid(B * NBY * NBX);   // 4096 blocks (16x16 tiles)
    dim3 block(256);
    bilerp_kernel<<<grid, block>>>(X, theta, out);
}